// round 10
// baseline (speedup 1.0000x reference)
#include <cuda_runtime.h>

#define BATCH 16
#define IMG_H 1024
#define IMG_W 1024
#define WPR   32                 // 32-bit words per row (1024/32)
#define NROWS (BATCH * IMG_H)
#define NWORDS (NROWS * WPR)     // 512K mask words
#define NTOT  ((double)BATCH * IMG_H * IMG_W)
#define ROWS_PER_BLK 8           // pack kernel rows/block
#define NBUCKET 32

// Scratch (allocation-free: __device__ globals). Zero-initialized at module
// load; the finalize path re-zeroes everything it used after each run, so
// every graph replay starts from a clean slate (no zero/accumulate race).
__device__ unsigned int g_lbits[NWORDS];        // label bits, 2 MB
__device__ unsigned int g_hbits[NWORDS];        // horizontal-OR (r=7) bits, 2 MB
__device__ unsigned int g_ebits[NWORDS];        // full 15x15-dilated bits, 2 MB
__device__ double g_sumB[NBUCKET][3];           // bucketed sums: All, Edge, Lab
__device__ int    g_cnt[2];                     // counts: Lab, Edge
__device__ int    g_done;                       // arrival counter

// ---------------------------------------------------------------------------
// Kernel A: 256 threads / 8 rows, front-batched int4 loads (measured 62%
// DRAM). Packs label bits + horizontal radius-7 OR. Each block contributes
// its label popcount with one atomic.
// ---------------------------------------------------------------------------
__global__ void __launch_bounds__(256) pack_hor(const int* __restrict__ label) {
    __shared__ unsigned int sw[ROWS_PER_BLK * WPR];
    const int t    = threadIdx.x;
    const int lane = t & 31;
    const int wid  = t >> 5;

    const int4* lab4 = (const int4*)label + (size_t)blockIdx.x * (ROWS_PER_BLK * WPR * 8);
    int4 v[8];
#pragma unroll
    for (int k = 0; k < 8; k++) v[k] = lab4[k * 256 + t];

#pragma unroll
    for (int k = 0; k < 8; k++) {
        unsigned int nib = (unsigned)v[k].x | ((unsigned)v[k].y << 1)
                         | ((unsigned)v[k].z << 2) | ((unsigned)v[k].w << 3);
        unsigned int val = nib << (4 * (lane & 7));
        val |= __shfl_xor_sync(0xffffffffu, val, 1);
        val |= __shfl_xor_sync(0xffffffffu, val, 2);
        val |= __shfl_xor_sync(0xffffffffu, val, 4);
        if ((lane & 7) == 0) sw[(k * 256 + t) >> 3] = val;
    }
    __syncthreads();

    const int w = t & 31;
    const unsigned int wl = (w > 0)       ? sw[t - 1] : 0u;
    const unsigned int wc = sw[t];
    const unsigned int wr = (w < WPR - 1) ? sw[t + 1] : 0u;
    unsigned long long a = (unsigned long long)wc | ((unsigned long long)wr << 32);
    a |= a >> 1; a |= a >> 2; a |= a >> 4;              // OR of px x..x+7
    unsigned long long c = (unsigned long long)wl | ((unsigned long long)wc << 32);
    c |= c << 1; c |= c << 2; c |= c << 4;              // OR of px x-7..x
    const size_t gidx = (size_t)blockIdx.x * (ROWS_PER_BLK * WPR) + t;
    g_lbits[gidx] = wc;
    g_hbits[gidx] = (unsigned int)a | (unsigned int)(c >> 32);

    // Label count: one atomic per block
    int c0 = __reduce_add_sync(0xffffffffu, __popc(wc));
    __shared__ int ic[8];
    if (lane == 0) ic[wid] = c0;
    __syncthreads();
    if (t == 0) {
        int s = 0;
#pragma unroll
        for (int i = 0; i < 8; i++) s += ic[i];
        atomicAdd(&g_cnt[0], s);
    }
}

// ---------------------------------------------------------------------------
// Kernel A2: vertical radius-7 OR. One output word per thread; the 15 input
// rows are L2-resident (4 MB dataset). Also contributes edge popcount.
// ---------------------------------------------------------------------------
__global__ void __launch_bounds__(256) vert_or() {
    const int t    = threadIdx.x;
    const int lane = t & 31;
    const int wid  = t >> 5;
    const int idx  = blockIdx.x * 256 + t;              // word index
    const int row  = idx >> 5;
    const int w    = idx & 31;
    const int y    = row & (IMG_H - 1);
    const int base = row - y;                           // image top row

    unsigned int e = 0;
#pragma unroll
    for (int dy = -7; dy <= 7; dy++) {
        const int yy = y + dy;
        if (yy >= 0 && yy < IMG_H)
            e |= g_hbits[(size_t)(base + yy) * WPR + w];
    }
    g_ebits[idx] = e;

    int c0 = __reduce_add_sync(0xffffffffu, __popc(e));
    __shared__ int ic[8];
    if (lane == 0) ic[wid] = c0;
    __syncthreads();
    if (t == 0) {
        int s = 0;
#pragma unroll
        for (int i = 0; i < 8; i++) s += ic[i];
        atomicAdd(&g_cnt[1], s);
    }
}

// ---------------------------------------------------------------------------
// Kernel B: pure streaming BCE. Thread i owns pixels 8i..8i+7 = byte i of
// lbits/ebits. 2x LDG.128 + 2x LDG.8 front-batched; no smem in the hot path,
// no shuffles/transposes, low regs -> high occupancy -> DRAM-bound.
// Last block finalizes AND resets all accumulator state for the next replay.
// ---------------------------------------------------------------------------
__global__ void __launch_bounds__(256) bce_kernel(const float* __restrict__ Pred,
                                                  float* __restrict__ out) {
    const int t    = threadIdx.x;
    const int lane = t & 31;
    const int wid  = t >> 5;
    const size_t i = (size_t)blockIdx.x * 256 + t;      // 8-px group index

    // Front-batched loads: 2x16B Pred + 1B lbits + 1B ebits
    const float4* p4 = (const float4*)Pred + 2 * i;
    const float4 pa = p4[0];
    const float4 pb = p4[1];
    const unsigned int lb = ((const unsigned char*)g_lbits)[i];
    const unsigned int eb = ((const unsigned char*)g_ebits)[i];

    float sAll = 0.f, sEdge = 0.f, sLab = 0.f;
#define PIX(pv, bit)                                               \
    {                                                              \
        const bool tl = (lb >> (bit)) & 1u;                        \
        const bool el = (eb >> (bit)) & 1u;                        \
        const float q  = tl ? (pv) : 1.0f - (pv);                  \
        const float l2 = __log2f(q);                               \
        sAll += l2;                                                \
        if (el) sEdge += l2;                                       \
        if (tl) sLab  += l2;                                       \
    }
    PIX(pa.x, 0) PIX(pa.y, 1) PIX(pa.z, 2) PIX(pa.w, 3)
    PIX(pb.x, 4) PIX(pb.y, 5) PIX(pb.z, 6) PIX(pb.w, 7)
#undef PIX

#pragma unroll
    for (int off = 16; off; off >>= 1) {
        sAll  += __shfl_xor_sync(0xffffffffu, sAll,  off);
        sEdge += __shfl_xor_sync(0xffffffffu, sEdge, off);
        sLab  += __shfl_xor_sync(0xffffffffu, sLab,  off);
    }

    __shared__ float fs[3][8];
    if (lane == 0) { fs[0][wid] = sAll; fs[1][wid] = sEdge; fs[2][wid] = sLab; }
    __syncthreads();

    __shared__ int amLast;
    if (t == 0) {
        double bA = 0, bE = 0, bL = 0;
#pragma unroll
        for (int k = 0; k < 8; k++) { bA += fs[0][k]; bE += fs[1][k]; bL += fs[2][k]; }
        const int bk = blockIdx.x & (NBUCKET - 1);      // spread atomic traffic
        atomicAdd(&g_sumB[bk][0], bA);
        atomicAdd(&g_sumB[bk][1], bE);
        atomicAdd(&g_sumB[bk][2], bL);
        __threadfence();
        amLast = (atomicAdd(&g_done, 1) == (int)gridDim.x - 1);
    }
    __syncthreads();

    if (amLast && wid == 0) {
        // Warp-parallel bucket reduction (lane L reads bucket L's 3 doubles)
        double a = g_sumB[lane][0];
        double e = g_sumB[lane][1];
        double l = g_sumB[lane][2];
        const int nL = g_cnt[0];
        const int nE = g_cnt[1];
#pragma unroll
        for (int off = 16; off; off >>= 1) {
            a += __shfl_xor_sync(0xffffffffu, a, off);
            e += __shfl_xor_sync(0xffffffffu, e, off);
            l += __shfl_xor_sync(0xffffffffu, l, off);
        }
        // Reset ALL accumulator state for the next graph replay
        g_sumB[lane][0] = 0.0;
        g_sumB[lane][1] = 0.0;
        g_sumB[lane][2] = 0.0;
        if (lane == 0) {
            g_cnt[0] = 0;
            g_cnt[1] = 0;
            g_done = 0;
            const double N  = NTOT;
            const double dL = (double)nL;                // label (E) count
            const double dE = (double)nE;                // edge count
            const double wE = (1.0 - dL / N) * 1.0;
            const double wB = (1.0 - (dE - dL) / N) * 0.8;
            const double wT = (1.0 - (N - dE) / N) * 0.5;
            // category sums of lg2 q:  E = l,  B = e - l,  T = a - e
            const double LN2 = 0.6931471805599453;
            out[0] = (float)(-LN2 * (wE * l + wB * (e - l) + wT * (a - e)) / N);
        }
    }
}

extern "C" void kernel_launch(void* const* d_in, const int* in_sizes, int n_in,
                              void* d_out, int out_size) {
    const float* Pred  = (const float*)d_in[0];
    const int*   label = (const int*)d_in[1];
    (void)in_sizes; (void)n_in; (void)out_size;

    pack_hor<<<NROWS / ROWS_PER_BLK, 256>>>(label);
    vert_or<<<NWORDS / 256, 256>>>();
    bce_kernel<<<(int)(NTOT / 8 / 256), 256>>>(Pred, (float*)d_out);
}

// round 11
// speedup vs baseline: 1.2745x; 1.2745x over previous
#include <cuda_runtime.h>

#define BATCH 16
#define IMG_H 1024
#define IMG_W 1024
#define WPR   32                 // 32-bit words per row (1024/32)
#define NROWS (BATCH * IMG_H)
#define NWORDS (NROWS * WPR)     // 512K mask words
#define NTOT  ((double)BATCH * IMG_H * IMG_W)
#define ROWS_PER_BLK 8           // pack kernel rows/block
#define NBUCKET 32

// Scratch (allocation-free: __device__ globals). Zero-initialized at module
// load; finalize re-zeroes everything after each run (replay-deterministic).
__device__ unsigned int g_lbits[NWORDS];        // label bits, 2 MB
__device__ unsigned int g_hbits[NWORDS];        // horizontal-OR (r=7) bits, 2 MB
__device__ unsigned int g_ebits[NWORDS];        // full 15x15-dilated bits, 2 MB
__device__ double g_sumB[NBUCKET][3];           // bucketed sums: All, Edge, Lab
__device__ int    g_cnt[2];                     // counts: Lab, Edge
__device__ int    g_done;                       // arrival counter

// ---------------------------------------------------------------------------
// Kernel A: 256 threads / 8 rows, front-batched streaming int4 loads.
// Packs label bits + horizontal radius-7 OR; one label-count atomic/block.
// ---------------------------------------------------------------------------
__global__ void __launch_bounds__(256) pack_hor(const int* __restrict__ label) {
    __shared__ unsigned int sw[ROWS_PER_BLK * WPR];
    const int t    = threadIdx.x;
    const int lane = t & 31;
    const int wid  = t >> 5;

    const int4* lab4 = (const int4*)label + (size_t)blockIdx.x * (ROWS_PER_BLK * WPR * 8);
    int4 v[8];
#pragma unroll
    for (int k = 0; k < 8; k++) v[k] = __ldcs(&lab4[k * 256 + t]);

#pragma unroll
    for (int k = 0; k < 8; k++) {
        unsigned int nib = (unsigned)v[k].x | ((unsigned)v[k].y << 1)
                         | ((unsigned)v[k].z << 2) | ((unsigned)v[k].w << 3);
        unsigned int val = nib << (4 * (lane & 7));
        val |= __shfl_xor_sync(0xffffffffu, val, 1);
        val |= __shfl_xor_sync(0xffffffffu, val, 2);
        val |= __shfl_xor_sync(0xffffffffu, val, 4);
        if ((lane & 7) == 0) sw[(k * 256 + t) >> 3] = val;
    }
    __syncthreads();

    const int w = t & 31;
    const unsigned int wl = (w > 0)       ? sw[t - 1] : 0u;
    const unsigned int wc = sw[t];
    const unsigned int wr = (w < WPR - 1) ? sw[t + 1] : 0u;
    unsigned long long a = (unsigned long long)wc | ((unsigned long long)wr << 32);
    a |= a >> 1; a |= a >> 2; a |= a >> 4;              // OR of px x..x+7
    unsigned long long c = (unsigned long long)wl | ((unsigned long long)wc << 32);
    c |= c << 1; c |= c << 2; c |= c << 4;              // OR of px x-7..x
    const size_t gidx = (size_t)blockIdx.x * (ROWS_PER_BLK * WPR) + t;
    g_lbits[gidx] = wc;
    g_hbits[gidx] = (unsigned int)a | (unsigned int)(c >> 32);

    int c0 = __reduce_add_sync(0xffffffffu, __popc(wc));
    __shared__ int ic[8];
    if (lane == 0) ic[wid] = c0;
    __syncthreads();
    if (t == 0) {
        int s = 0;
#pragma unroll
        for (int i = 0; i < 8; i++) s += ic[i];
        atomicAdd(&g_cnt[0], s);
    }
}

// ---------------------------------------------------------------------------
// Kernel A2: vertical radius-7 OR (hbits -> ebits). 15 input rows are
// L2-resident (4 MB dataset). Contributes edge popcount (1 atomic/block).
// ---------------------------------------------------------------------------
__global__ void __launch_bounds__(256) vert_or() {
    const int t    = threadIdx.x;
    const int lane = t & 31;
    const int wid  = t >> 5;
    const int idx  = blockIdx.x * 256 + t;
    const int row  = idx >> 5;
    const int w    = idx & 31;
    const int y    = row & (IMG_H - 1);
    const int base = row - y;

    unsigned int e = 0;
#pragma unroll
    for (int dy = -7; dy <= 7; dy++) {
        const int yy = y + dy;
        if (yy >= 0 && yy < IMG_H)
            e |= g_hbits[(size_t)(base + yy) * WPR + w];
    }
    g_ebits[idx] = e;

    int c0 = __reduce_add_sync(0xffffffffu, __popc(e));
    __shared__ int ic[8];
    if (lane == 0) ic[wid] = c0;
    __syncthreads();
    if (t == 0) {
        int s = 0;
#pragma unroll
        for (int i = 0; i < 8; i++) s += ic[i];
        atomicAdd(&g_cnt[1], s);
    }
}

// ---------------------------------------------------------------------------
// Kernel B: warp = one image row (32 px/lane). 8 front-batched streaming
// LDG.128 (proven 61%-DRAM shape), masks via 2 coalesced word loads + 16
// shuffles (one-shot transpose), then pure immediate-bit-test compute.
// No smem, no popc, no vertical OR. Last block finalizes and resets state.
// ---------------------------------------------------------------------------
__global__ void __launch_bounds__(256) bce_kernel(const float* __restrict__ Pred,
                                                  float* __restrict__ out) {
    const int t    = threadIdx.x;
    const int lane = t & 31;
    const int wid  = t >> 5;
    const int row  = blockIdx.x * 8 + wid;

    // Front-batched: 8x LDG.128 streaming + 2 mask words
    const float4* prow = (const float4*)(Pred + (size_t)row * IMG_W);
    float4 p[8];
#pragma unroll
    for (int k = 0; k < 8; k++) p[k] = __ldcs(&prow[k * 32 + lane]);
    const unsigned int lw = g_lbits[(size_t)row * WPR + lane];
    const unsigned int ew = g_ebits[(size_t)row * WPR + lane];

    // Transpose: lane's pixel i (=4k+j) is word 4k+(lane>>3), nib 4*(lane&7)
    unsigned int mylw = 0, myew = 0;
    const int nsh = 4 * (lane & 7);
#pragma unroll
    for (int k = 0; k < 8; k++) {
        const int widx = 4 * k + (lane >> 3);
        mylw |= ((__shfl_sync(0xffffffffu, lw, widx) >> nsh) & 0xFu) << (4 * k);
        myew |= ((__shfl_sync(0xffffffffu, ew, widx) >> nsh) & 0xFu) << (4 * k);
    }

    float sAll = 0.f, sEdge = 0.f, sLab = 0.f;
#define PIX(pv, bit)                                               \
    {                                                              \
        const bool tl = (mylw >> (bit)) & 1u;                      \
        const bool el = (myew >> (bit)) & 1u;                      \
        const float q  = tl ? (pv) : 1.0f - (pv);                  \
        const float l2 = __log2f(q);                               \
        sAll += l2;                                                \
        if (el) sEdge += l2;                                       \
        if (tl) sLab  += l2;                                       \
    }
#pragma unroll
    for (int k = 0; k < 8; k++) {
        PIX(p[k].x, 4 * k + 0)
        PIX(p[k].y, 4 * k + 1)
        PIX(p[k].z, 4 * k + 2)
        PIX(p[k].w, 4 * k + 3)
    }
#undef PIX

#pragma unroll
    for (int off = 16; off; off >>= 1) {
        sAll  += __shfl_xor_sync(0xffffffffu, sAll,  off);
        sEdge += __shfl_xor_sync(0xffffffffu, sEdge, off);
        sLab  += __shfl_xor_sync(0xffffffffu, sLab,  off);
    }

    __shared__ float fs[3][8];
    if (lane == 0) { fs[0][wid] = sAll; fs[1][wid] = sEdge; fs[2][wid] = sLab; }
    __syncthreads();

    __shared__ int amLast;
    if (t == 0) {
        double bA = 0, bE = 0, bL = 0;
#pragma unroll
        for (int k = 0; k < 8; k++) { bA += fs[0][k]; bE += fs[1][k]; bL += fs[2][k]; }
        const int bk = blockIdx.x & (NBUCKET - 1);      // spread atomic traffic
        atomicAdd(&g_sumB[bk][0], bA);
        atomicAdd(&g_sumB[bk][1], bE);
        atomicAdd(&g_sumB[bk][2], bL);
        __threadfence();
        amLast = (atomicAdd(&g_done, 1) == (int)gridDim.x - 1);
    }
    __syncthreads();

    if (amLast && wid == 0) {
        double a = g_sumB[lane][0];
        double e = g_sumB[lane][1];
        double l = g_sumB[lane][2];
        const int nL = g_cnt[0];
        const int nE = g_cnt[1];
#pragma unroll
        for (int off = 16; off; off >>= 1) {
            a += __shfl_xor_sync(0xffffffffu, a, off);
            e += __shfl_xor_sync(0xffffffffu, e, off);
            l += __shfl_xor_sync(0xffffffffu, l, off);
        }
        // Reset ALL accumulator state for the next graph replay
        g_sumB[lane][0] = 0.0;
        g_sumB[lane][1] = 0.0;
        g_sumB[lane][2] = 0.0;
        if (lane == 0) {
            g_cnt[0] = 0;
            g_cnt[1] = 0;
            g_done = 0;
            const double N  = NTOT;
            const double dL = (double)nL;                // label (E) count
            const double dE = (double)nE;                // edge count
            const double wE = (1.0 - dL / N) * 1.0;
            const double wB = (1.0 - (dE - dL) / N) * 0.8;
            const double wT = (1.0 - (N - dE) / N) * 0.5;
            // category sums of lg2 q:  E = l,  B = e - l,  T = a - e
            const double LN2 = 0.6931471805599453;
            out[0] = (float)(-LN2 * (wE * l + wB * (e - l) + wT * (a - e)) / N);
        }
    }
}

extern "C" void kernel_launch(void* const* d_in, const int* in_sizes, int n_in,
                              void* d_out, int out_size) {
    const float* Pred  = (const float*)d_in[0];
    const int*   label = (const int*)d_in[1];
    (void)in_sizes; (void)n_in; (void)out_size;

    pack_hor<<<NROWS / ROWS_PER_BLK, 256>>>(label);
    vert_or<<<NWORDS / 256, 256>>>();
    bce_kernel<<<NROWS / 8, 256>>>(Pred, (float*)d_out);
}

// round 12
// speedup vs baseline: 1.6160x; 1.2680x over previous
#include <cuda_runtime.h>

#define BATCH 16
#define IMG_H 1024
#define IMG_W 1024
#define WPR   32                 // 32-bit words per row (1024/32)
#define NROWS (BATCH * IMG_H)
#define NWORDS (NROWS * WPR)
#define NTOT  ((double)BATCH * IMG_H * IMG_W)
#define ROWS_PER_BLK 8
#define NBUCKET 32

// Scratch (allocation-free: __device__ globals). Zero-initialized at module
// load; finalize re-zeroes everything after each run (replay-deterministic).
__device__ unsigned int g_hbits[NWORDS];        // horizontal-OR (r=7) bits, 2 MB
__device__ unsigned int g_lmix[NWORDS];         // LANE-REMIXED label bits, 2 MB
__device__ double g_sumB[NBUCKET][3];           // bucketed sums: All, Edge, Lab
__device__ int    g_cnt[2];                     // counts: Lab, Edge
__device__ int    g_done;                       // arrival counter

// Remix layout: for row r, lane L, pixel i = 4k+j (k=0..7, j=0..3) lives at
// image column 128k + 4L + j  ->  bit 4(L&7)+j of row-word 4k+(L>>3).
// g_lmix[r*32+L] bit i == label bit of that pixel. Consumers do ONE coalesced
// load instead of a 16-shuffle transpose.

// ---------------------------------------------------------------------------
// Kernel A: 256 threads / 8 rows, front-batched streaming int4 loads.
// Produces hbits (horizontal r=7 OR) + lane-remixed label words + label count.
// ---------------------------------------------------------------------------
__global__ void __launch_bounds__(256) pack_hor(const int* __restrict__ label) {
    __shared__ unsigned int sw[ROWS_PER_BLK * WPR];
    const int t    = threadIdx.x;
    const int lane = t & 31;
    const int wid  = t >> 5;

    const int4* lab4 = (const int4*)label + (size_t)blockIdx.x * (ROWS_PER_BLK * WPR * 8);
    int4 v[8];
#pragma unroll
    for (int k = 0; k < 8; k++) v[k] = __ldcs(&lab4[k * 256 + t]);

#pragma unroll
    for (int k = 0; k < 8; k++) {
        unsigned int nib = (unsigned)v[k].x | ((unsigned)v[k].y << 1)
                         | ((unsigned)v[k].z << 2) | ((unsigned)v[k].w << 3);
        unsigned int val = nib << (4 * (lane & 7));
        val |= __shfl_xor_sync(0xffffffffu, val, 1);
        val |= __shfl_xor_sync(0xffffffffu, val, 2);
        val |= __shfl_xor_sync(0xffffffffu, val, 4);
        if ((lane & 7) == 0) sw[(k * 256 + t) >> 3] = val;
    }
    __syncthreads();

    // t = r*32 + w  (r = row-in-block, w = word-in-row = lane)
    const int w = lane;
    const int rbase = t & ~31;                           // r*32
    const unsigned int wl = (w > 0)       ? sw[t - 1] : 0u;
    const unsigned int wc = sw[t];
    const unsigned int wr = (w < WPR - 1) ? sw[t + 1] : 0u;
    unsigned long long a = (unsigned long long)wc | ((unsigned long long)wr << 32);
    a |= a >> 1; a |= a >> 2; a |= a >> 4;              // OR of px x..x+7
    unsigned long long c = (unsigned long long)wl | ((unsigned long long)wc << 32);
    c |= c << 1; c |= c << 2; c |= c << 4;              // OR of px x-7..x
    const size_t gidx = (size_t)blockIdx.x * (ROWS_PER_BLK * WPR) + t;
    g_hbits[gidx] = (unsigned int)a | (unsigned int)(c >> 32);

    // Lane-remix of label words via broadcast smem reads (role L = w)
    unsigned int lmix = 0;
    const int nsh = 4 * (w & 7);
#pragma unroll
    for (int k = 0; k < 8; k++)
        lmix |= ((sw[rbase + 4 * k + (w >> 3)] >> nsh) & 0xFu) << (4 * k);
    g_lmix[gidx] = lmix;

    // Label count (popc over own word wc): one atomic per block
    int c0 = __reduce_add_sync(0xffffffffu, __popc(wc));
    __shared__ int ic[8];
    if (lane == 0) ic[wid] = c0;
    __syncthreads();
    if (t == 0) {
        int s = 0;
#pragma unroll
        for (int i = 0; i < 8; i++) s += ic[i];
        atomicAdd(&g_cnt[0], s);
    }
}

// ---------------------------------------------------------------------------
// Kernel B: fused vertical-OR + BCE. Warp = one image row; lane = word/quad.
// Front-batched: 8x LDG.128 Pred (streaming) + lmix + 15 coalesced L2-hot
// hbits loads (vertical OR in-register). Edge remix = 8 INDEPENDENT shuffles.
// No smem staging, no serial transpose chain, 4-way split sAll accumulator.
// Last block finalizes and resets all state.
// ---------------------------------------------------------------------------
__global__ void __launch_bounds__(256) bce_kernel(const float* __restrict__ Pred,
                                                  float* __restrict__ out) {
    const int t    = threadIdx.x;
    const int lane = t & 31;
    const int wid  = t >> 5;
    const int row  = blockIdx.x * 8 + wid;
    const int y    = row & (IMG_H - 1);
    const int base = row - y;                            // image top row

    // Front-batch everything: Pred (DRAM) + masks
    const float4* prow = (const float4*)(Pred + (size_t)row * IMG_W);
    float4 p[8];
#pragma unroll
    for (int k = 0; k < 8; k++) p[k] = __ldcs(&prow[k * 32 + lane]);
    const unsigned int mylw = g_lmix[(size_t)row * WPR + lane];

    // Vertical r=7 OR straight from L2 (15 independent coalesced loads)
    unsigned int ew = 0;
#pragma unroll
    for (int dy = -7; dy <= 7; dy++) {
        const int yy = y + dy;
        if (yy >= 0 && yy < IMG_H)
            ew |= g_hbits[(size_t)(base + yy) * WPR + lane];
    }
    const int cEdge = __reduce_add_sync(0xffffffffu, __popc(ew));

    // Edge remix: 8 independent shuffles (no serial chain)
    unsigned int myew = 0;
    const int nsh = 4 * (lane & 7);
#pragma unroll
    for (int k = 0; k < 8; k++)
        myew |= ((__shfl_sync(0xffffffffu, ew, 4 * k + (lane >> 3)) >> nsh) & 0xFu) << (4 * k);

    // Compute: 4-way split sAll breaks the FADD chain
    float sA0 = 0.f, sA1 = 0.f, sA2 = 0.f, sA3 = 0.f;
    float sEdge = 0.f, sLab = 0.f;
#define PIX(pv, bit, sA)                                           \
    {                                                              \
        const bool tl = (mylw >> (bit)) & 1u;                      \
        const bool el = (myew >> (bit)) & 1u;                      \
        const float q  = tl ? (pv) : 1.0f - (pv);                  \
        const float l2 = __log2f(q);                               \
        sA += l2;                                                  \
        if (el) sEdge += l2;                                       \
        if (tl) sLab  += l2;                                       \
    }
#pragma unroll
    for (int k = 0; k < 8; k++) {
        PIX(p[k].x, 4 * k + 0, sA0)
        PIX(p[k].y, 4 * k + 1, sA1)
        PIX(p[k].z, 4 * k + 2, sA2)
        PIX(p[k].w, 4 * k + 3, sA3)
    }
#undef PIX
    float sAll = (sA0 + sA1) + (sA2 + sA3);

#pragma unroll
    for (int off = 16; off; off >>= 1) {
        sAll  += __shfl_xor_sync(0xffffffffu, sAll,  off);
        sEdge += __shfl_xor_sync(0xffffffffu, sEdge, off);
        sLab  += __shfl_xor_sync(0xffffffffu, sLab,  off);
    }

    __shared__ float fs[3][8];
    __shared__ int   ie[8];
    if (lane == 0) {
        fs[0][wid] = sAll; fs[1][wid] = sEdge; fs[2][wid] = sLab;
        ie[wid] = cEdge;
    }
    __syncthreads();

    __shared__ int amLast;
    if (t == 0) {
        double bA = 0, bE = 0, bL = 0; int iE = 0;
#pragma unroll
        for (int k = 0; k < 8; k++) {
            bA += fs[0][k]; bE += fs[1][k]; bL += fs[2][k]; iE += ie[k];
        }
        const int bk = blockIdx.x & (NBUCKET - 1);      // spread atomic traffic
        atomicAdd(&g_sumB[bk][0], bA);
        atomicAdd(&g_sumB[bk][1], bE);
        atomicAdd(&g_sumB[bk][2], bL);
        atomicAdd(&g_cnt[1], iE);
        __threadfence();
        amLast = (atomicAdd(&g_done, 1) == (int)gridDim.x - 1);
    }
    __syncthreads();

    if (amLast && wid == 0) {
        double a = g_sumB[lane][0];
        double e = g_sumB[lane][1];
        double l = g_sumB[lane][2];
        const int nL = g_cnt[0];
        const int nE = g_cnt[1];
#pragma unroll
        for (int off = 16; off; off >>= 1) {
            a += __shfl_xor_sync(0xffffffffu, a, off);
            e += __shfl_xor_sync(0xffffffffu, e, off);
            l += __shfl_xor_sync(0xffffffffu, l, off);
        }
        // Reset ALL accumulator state for the next graph replay
        g_sumB[lane][0] = 0.0;
        g_sumB[lane][1] = 0.0;
        g_sumB[lane][2] = 0.0;
        if (lane == 0) {
            g_cnt[0] = 0;
            g_cnt[1] = 0;
            g_done = 0;
            const double N  = NTOT;
            const double dL = (double)nL;                // label (E) count
            const double dE = (double)nE;                // edge count
            const double wE = (1.0 - dL / N) * 1.0;
            const double wB = (1.0 - (dE - dL) / N) * 0.8;
            const double wT = (1.0 - (N - dE) / N) * 0.5;
            // category sums of lg2 q:  E = l,  B = e - l,  T = a - e
            const double LN2 = 0.6931471805599453;
            out[0] = (float)(-LN2 * (wE * l + wB * (e - l) + wT * (a - e)) / N);
        }
    }
}

extern "C" void kernel_launch(void* const* d_in, const int* in_sizes, int n_in,
                              void* d_out, int out_size) {
    const float* Pred  = (const float*)d_in[0];
    const int*   label = (const int*)d_in[1];
    (void)in_sizes; (void)n_in; (void)out_size;

    pack_hor<<<NROWS / ROWS_PER_BLK, 256>>>(label);
    bce_kernel<<<NROWS / 8, 256>>>(Pred, (float*)d_out);
}